// round 13
// baseline (speedup 1.0000x reference)
#include <cuda_runtime.h>
#include <cstdint>

// ---------------------------------------------------------------------------
// HQNN: 3x (Dense+tanh -> 4-qubit RX/CNOT circuit).
// Analytic multilinear reformulation (supports T0={0,1,3} T1={0,2,3}
// T2={1,3} T3={0,2}); coefficients probed per launch by a tiny setup kernel.
// R9: 4 rows per thread, constant-major scheduling so each LDCU feeds 4 FFMAs
// (sm_103a has no cbank-fused FFMA operands; constant reads are explicit LDCU
// and dominated the issue stream at R=1).
// ---------------------------------------------------------------------------

struct ConstsLayout {
    float C[3][16][4];   // probe table: C[layer][mask][wire]
    float W0[16][4];
    float b0[4];
    float W1[4][4];
    float b1[4];
    float W2[4][4];
    float b2[4];
};   // 300 floats

__device__ float g_stage[300];
__constant__ ConstsLayout cK;

// ------------------------- setup: probe simulations ------------------------

__device__ void rx_apply(float* re, float* im, float ang, int w) {
    float c = cosf(0.5f * ang);
    float s = sinf(0.5f * ang);
    int bit = 1 << w;
    for (int b = 0; b < 16; b++) {
        if (b & bit) continue;
        int b1 = b | bit;
        float r0 = re[b], i0 = im[b], r1 = re[b1], i1 = im[b1];
        re[b]  = c * r0 + s * i1;
        im[b]  = c * i0 - s * r1;
        re[b1] = c * r1 + s * i0;
        im[b1] = c * i1 - s * r0;
    }
}

__device__ void cnot_apply(float* re, float* im, int cw, int tw) {
    int cb = 1 << cw, tb = 1 << tw;
    for (int b = 0; b < 16; b++) {
        if ((b & cb) && !(b & tb)) {
            int b1 = b | tb;
            float t;
            t = re[b]; re[b] = re[b1]; re[b1] = t;
            t = im[b]; im[b] = im[b1]; im[b1] = t;
        }
    }
}

__global__ void hqnn_setup(const float* __restrict__ theta,
                           const float* __restrict__ W0, const float* __restrict__ b0,
                           const float* __restrict__ W1, const float* __restrict__ b1,
                           const float* __restrict__ W2, const float* __restrict__ b2) {
    int t = threadIdx.x;
    if (t < 48) {
        int l = t >> 4;      // hybrid layer 0..2
        int m = t & 15;      // probe mask over 4 wires
        float re[16], im[16];
        #pragma unroll
        for (int i = 0; i < 16; i++) { re[i] = 0.f; im[i] = 0.f; }
        re[0] = 1.f;
        for (int w = 0; w < 4; w++) {
            float a = ((m >> w) & 1) ? 1.57079632679489662f : 0.0f;
            rx_apply(re, im, a, w);
        }
        for (int e = 0; e < 2; e++) {
            for (int w = 0; w < 4; w++)
                rx_apply(re, im, theta[l * 8 + e * 4 + w], w);
            for (int w = 0; w < 4; w++)
                cnot_apply(re, im, w, (w + 1) & 3);
        }
        for (int w = 0; w < 4; w++) {
            float z = 0.f;
            for (int b = 0; b < 16; b++) {
                float p = re[b] * re[b] + im[b] * im[b];
                z += ((b >> w) & 1) ? -p : p;
            }
            g_stage[(l * 16 + m) * 4 + w] = z;
        }
    }
    for (int i = t; i < 108; i += blockDim.x) {
        float v;
        if (i < 64)       v = W0[i];
        else if (i < 68)  v = b0[i - 64];
        else if (i < 84)  v = W1[i - 68];
        else if (i < 88)  v = b1[i - 84];
        else if (i < 104) v = W2[i - 88];
        else              v = b2[i - 104];
        g_stage[192 + i] = v;
    }
}

// ------------------------------ main kernel --------------------------------

#define R 4   // rows per thread

__device__ __forceinline__ float tanh_fast(float x) {
    float e = __expf(2.0f * x);
    return 1.0f - __fdividef(2.0f, e + 1.0f);
}

// Constant-major 4-row circuit evaluation. h[r][wire] in, o[r][wire] out.
__device__ __forceinline__ void qcirc4(const float (&C)[16][4],
                                       const float (&h)[R][4], float (&o)[R][4]) {
    float s[4][R], c[4][R];   // [wire][row]
    #pragma unroll
    for (int r = 0; r < R; r++) {
        #pragma unroll
        for (int w = 0; w < 4; w++)
            __sincosf(h[r][w], &s[w][r], &c[w][r]);
    }

    // out0: wires {0,1,3}
    {
        float p00[R], p10[R], p01[R], p11[R], A[R], Bv[R];
        #pragma unroll
        for (int r = 0; r < R; r++) {
            p00[r] = c[0][r] * c[1][r];
            p10[r] = s[0][r] * c[1][r];
            p01[r] = c[0][r] * s[1][r];
            p11[r] = s[0][r] * s[1][r];
        }
        float k0 = C[0][0], k1 = C[1][0], k2 = C[2][0], k3 = C[3][0];
        float k8 = C[8][0], k9 = C[9][0], k10 = C[10][0], k11 = C[11][0];
        #pragma unroll
        for (int r = 0; r < R; r++) {
            float a = k0 * p00[r];
            a = fmaf(k1, p10[r], a);
            a = fmaf(k2, p01[r], a);
            a = fmaf(k3, p11[r], a);
            A[r] = a;
            float b = k8 * p00[r];
            b = fmaf(k9,  p10[r], b);
            b = fmaf(k10, p01[r], b);
            b = fmaf(k11, p11[r], b);
            Bv[r] = b;
            o[r][0] = fmaf(Bv[r], s[3][r], A[r] * c[3][r]);
        }
    }

    // out1: wires {0,2,3}
    {
        float q00[R], q10[R], q01[R], q11[R];
        #pragma unroll
        for (int r = 0; r < R; r++) {
            q00[r] = c[2][r] * c[3][r];
            q10[r] = s[2][r] * c[3][r];
            q01[r] = c[2][r] * s[3][r];
            q11[r] = s[2][r] * s[3][r];
        }
        float k0 = C[0][1], k4 = C[4][1], k8 = C[8][1], k12 = C[12][1];
        float k1 = C[1][1], k5 = C[5][1], k9 = C[9][1], k13 = C[13][1];
        #pragma unroll
        for (int r = 0; r < R; r++) {
            float a = k0 * q00[r];
            a = fmaf(k4,  q10[r], a);
            a = fmaf(k8,  q01[r], a);
            a = fmaf(k12, q11[r], a);
            float b = k1 * q00[r];
            b = fmaf(k5,  q10[r], b);
            b = fmaf(k9,  q01[r], b);
            b = fmaf(k13, q11[r], b);
            o[r][1] = fmaf(b, s[0][r], a * c[0][r]);
        }
    }

    // out2: wires {1,3}
    {
        float k0 = C[0][2], k2 = C[2][2], k8 = C[8][2], k10 = C[10][2];
        #pragma unroll
        for (int r = 0; r < R; r++) {
            float v = k0 * (c[1][r] * c[3][r]);
            v = fmaf(k2,  s[1][r] * c[3][r], v);
            v = fmaf(k8,  c[1][r] * s[3][r], v);
            v = fmaf(k10, s[1][r] * s[3][r], v);
            o[r][2] = v;
        }
    }

    // out3: wires {0,2}
    {
        float k0 = C[0][3], k1 = C[1][3], k4 = C[4][3], k5 = C[5][3];
        #pragma unroll
        for (int r = 0; r < R; r++) {
            float v = k0 * (c[0][r] * c[2][r]);
            v = fmaf(k1, s[0][r] * c[2][r], v);
            v = fmaf(k4, c[0][r] * s[2][r], v);
            v = fmaf(k5, s[0][r] * s[2][r], v);
            o[r][3] = v;
        }
    }
}

__global__ void __launch_bounds__(128, 4) hqnn_main(const float4* __restrict__ xv,
                                                    float4* __restrict__ out, int B) {
    int base = blockIdx.x * (128 * R) + threadIdx.x;

    int rows[R];
    #pragma unroll
    for (int k = 0; k < R; k++) rows[k] = base + k * 128;

    // Front-batched input load (MLP = 16 LDG.128)
    float Xs[R][16];
    #pragma unroll
    for (int k = 0; k < R; k++) {
        if (rows[k] < B) {
            const float4* p = xv + (size_t)rows[k] * 4;
            float4 a = p[0], b = p[1], cc = p[2], d = p[3];
            Xs[k][0]  = a.x;  Xs[k][1]  = a.y;  Xs[k][2]  = a.z;  Xs[k][3]  = a.w;
            Xs[k][4]  = b.x;  Xs[k][5]  = b.y;  Xs[k][6]  = b.z;  Xs[k][7]  = b.w;
            Xs[k][8]  = cc.x; Xs[k][9]  = cc.y; Xs[k][10] = cc.z; Xs[k][11] = cc.w;
            Xs[k][12] = d.x;  Xs[k][13] = d.y;  Xs[k][14] = d.z;  Xs[k][15] = d.w;
        } else {
            #pragma unroll
            for (int i = 0; i < 16; i++) Xs[k][i] = 0.f;
        }
    }

    // dense0 (16 -> 4), constant-major: one LDCU feeds R FFMAs
    float acc[R][4];
    #pragma unroll
    for (int j = 0; j < 4; j++) {
        float bj = cK.b0[j];
        #pragma unroll
        for (int r = 0; r < R; r++) acc[r][j] = bj;
    }
    #pragma unroll
    for (int i = 0; i < 16; i++) {
        #pragma unroll
        for (int j = 0; j < 4; j++) {
            float w = cK.W0[i][j];
            #pragma unroll
            for (int r = 0; r < R; r++)
                acc[r][j] = fmaf(Xs[r][i], w, acc[r][j]);
        }
    }

    float h[R][4], o[R][4];
    #pragma unroll
    for (int r = 0; r < R; r++)
        #pragma unroll
        for (int j = 0; j < 4; j++)
            h[r][j] = tanh_fast(acc[r][j]);

    qcirc4(cK.C[0], h, o);

    // dense1 (4 -> 4) + tanh
    #pragma unroll
    for (int j = 0; j < 4; j++) {
        float bj = cK.b1[j];
        #pragma unroll
        for (int r = 0; r < R; r++) acc[r][j] = bj;
    }
    #pragma unroll
    for (int i = 0; i < 4; i++) {
        #pragma unroll
        for (int j = 0; j < 4; j++) {
            float w = cK.W1[i][j];
            #pragma unroll
            for (int r = 0; r < R; r++)
                acc[r][j] = fmaf(o[r][i], w, acc[r][j]);
        }
    }
    #pragma unroll
    for (int r = 0; r < R; r++)
        #pragma unroll
        for (int j = 0; j < 4; j++)
            h[r][j] = tanh_fast(acc[r][j]);

    qcirc4(cK.C[1], h, o);

    // dense2 (4 -> 4) + tanh
    #pragma unroll
    for (int j = 0; j < 4; j++) {
        float bj = cK.b2[j];
        #pragma unroll
        for (int r = 0; r < R; r++) acc[r][j] = bj;
    }
    #pragma unroll
    for (int i = 0; i < 4; i++) {
        #pragma unroll
        for (int j = 0; j < 4; j++) {
            float w = cK.W2[i][j];
            #pragma unroll
            for (int r = 0; r < R; r++)
                acc[r][j] = fmaf(o[r][i], w, acc[r][j]);
        }
    }
    #pragma unroll
    for (int r = 0; r < R; r++)
        #pragma unroll
        for (int j = 0; j < 4; j++)
            h[r][j] = tanh_fast(acc[r][j]);

    qcirc4(cK.C[2], h, o);

    #pragma unroll
    for (int k = 0; k < R; k++) {
        if (rows[k] < B)
            out[rows[k]] = make_float4(o[k][0], o[k][1], o[k][2], o[k][3]);
    }
}

// ------------------------------ launch --------------------------------------

extern "C" void kernel_launch(void* const* d_in, const int* in_sizes, int n_in,
                              void* d_out, int out_size) {
    const float* x     = (const float*)d_in[0];
    const float* theta = (const float*)d_in[1];
    const float* W0    = (const float*)d_in[2];
    const float* b0    = (const float*)d_in[3];
    const float* W1    = (const float*)d_in[4];
    const float* b1    = (const float*)d_in[5];
    const float* W2    = (const float*)d_in[6];
    const float* b2    = (const float*)d_in[7];
    int B = in_sizes[0] / 16;

    hqnn_setup<<<1, 128>>>(theta, W0, b0, W1, b1, W2, b2);

    void* stage_ptr = nullptr;
    cudaGetSymbolAddress(&stage_ptr, g_stage);
    cudaMemcpyToSymbolAsync(cK, stage_ptr, sizeof(ConstsLayout), 0,
                            cudaMemcpyDeviceToDevice, 0);

    int rowsPerBlock = 128 * R;
    int blocks = (B + rowsPerBlock - 1) / rowsPerBlock;
    hqnn_main<<<blocks, 128>>>((const float4*)x, (float4*)d_out, B);
}

// round 14
// speedup vs baseline: 1.0017x; 1.0017x over previous
#include <cuda_runtime.h>
#include <cstdint>

// ---------------------------------------------------------------------------
// HQNN: 3x (Dense+tanh -> 4-qubit RX/CNOT circuit).
// Analytic multilinear reformulation (supports T0={0,1,3} T1={0,2,3}
// T2={1,3} T3={0,2}); coefficients probed per launch by a tiny setup kernel.
// R9: 4 rows per thread, constant-major scheduling so each LDCU feeds 4 FFMAs
// (sm_103a has no cbank-fused FFMA operands; constant reads are explicit LDCU
// and dominated the issue stream at R=1).
// ---------------------------------------------------------------------------

struct ConstsLayout {
    float C[3][16][4];   // probe table: C[layer][mask][wire]
    float W0[16][4];
    float b0[4];
    float W1[4][4];
    float b1[4];
    float W2[4][4];
    float b2[4];
};   // 300 floats

__device__ float g_stage[300];
__constant__ ConstsLayout cK;

// ------------------------- setup: probe simulations ------------------------

__device__ void rx_apply(float* re, float* im, float ang, int w) {
    float c = cosf(0.5f * ang);
    float s = sinf(0.5f * ang);
    int bit = 1 << w;
    for (int b = 0; b < 16; b++) {
        if (b & bit) continue;
        int b1 = b | bit;
        float r0 = re[b], i0 = im[b], r1 = re[b1], i1 = im[b1];
        re[b]  = c * r0 + s * i1;
        im[b]  = c * i0 - s * r1;
        re[b1] = c * r1 + s * i0;
        im[b1] = c * i1 - s * r0;
    }
}

__device__ void cnot_apply(float* re, float* im, int cw, int tw) {
    int cb = 1 << cw, tb = 1 << tw;
    for (int b = 0; b < 16; b++) {
        if ((b & cb) && !(b & tb)) {
            int b1 = b | tb;
            float t;
            t = re[b]; re[b] = re[b1]; re[b1] = t;
            t = im[b]; im[b] = im[b1]; im[b1] = t;
        }
    }
}

__global__ void hqnn_setup(const float* __restrict__ theta,
                           const float* __restrict__ W0, const float* __restrict__ b0,
                           const float* __restrict__ W1, const float* __restrict__ b1,
                           const float* __restrict__ W2, const float* __restrict__ b2) {
    int t = threadIdx.x;
    if (t < 48) {
        int l = t >> 4;      // hybrid layer 0..2
        int m = t & 15;      // probe mask over 4 wires
        float re[16], im[16];
        #pragma unroll
        for (int i = 0; i < 16; i++) { re[i] = 0.f; im[i] = 0.f; }
        re[0] = 1.f;
        for (int w = 0; w < 4; w++) {
            float a = ((m >> w) & 1) ? 1.57079632679489662f : 0.0f;
            rx_apply(re, im, a, w);
        }
        for (int e = 0; e < 2; e++) {
            for (int w = 0; w < 4; w++)
                rx_apply(re, im, theta[l * 8 + e * 4 + w], w);
            for (int w = 0; w < 4; w++)
                cnot_apply(re, im, w, (w + 1) & 3);
        }
        for (int w = 0; w < 4; w++) {
            float z = 0.f;
            for (int b = 0; b < 16; b++) {
                float p = re[b] * re[b] + im[b] * im[b];
                z += ((b >> w) & 1) ? -p : p;
            }
            g_stage[(l * 16 + m) * 4 + w] = z;
        }
    }
    for (int i = t; i < 108; i += blockDim.x) {
        float v;
        if (i < 64)       v = W0[i];
        else if (i < 68)  v = b0[i - 64];
        else if (i < 84)  v = W1[i - 68];
        else if (i < 88)  v = b1[i - 84];
        else if (i < 104) v = W2[i - 88];
        else              v = b2[i - 104];
        g_stage[192 + i] = v;
    }
}

// ------------------------------ main kernel --------------------------------

#define R 4   // rows per thread

__device__ __forceinline__ float tanh_fast(float x) {
    float e = __expf(2.0f * x);
    return 1.0f - __fdividef(2.0f, e + 1.0f);
}

// Constant-major 4-row circuit evaluation. h[r][wire] in, o[r][wire] out.
__device__ __forceinline__ void qcirc4(const float (&C)[16][4],
                                       const float (&h)[R][4], float (&o)[R][4]) {
    float s[4][R], c[4][R];   // [wire][row]
    #pragma unroll
    for (int r = 0; r < R; r++) {
        #pragma unroll
        for (int w = 0; w < 4; w++)
            __sincosf(h[r][w], &s[w][r], &c[w][r]);
    }

    // out0: wires {0,1,3}
    {
        float p00[R], p10[R], p01[R], p11[R], A[R], Bv[R];
        #pragma unroll
        for (int r = 0; r < R; r++) {
            p00[r] = c[0][r] * c[1][r];
            p10[r] = s[0][r] * c[1][r];
            p01[r] = c[0][r] * s[1][r];
            p11[r] = s[0][r] * s[1][r];
        }
        float k0 = C[0][0], k1 = C[1][0], k2 = C[2][0], k3 = C[3][0];
        float k8 = C[8][0], k9 = C[9][0], k10 = C[10][0], k11 = C[11][0];
        #pragma unroll
        for (int r = 0; r < R; r++) {
            float a = k0 * p00[r];
            a = fmaf(k1, p10[r], a);
            a = fmaf(k2, p01[r], a);
            a = fmaf(k3, p11[r], a);
            A[r] = a;
            float b = k8 * p00[r];
            b = fmaf(k9,  p10[r], b);
            b = fmaf(k10, p01[r], b);
            b = fmaf(k11, p11[r], b);
            Bv[r] = b;
            o[r][0] = fmaf(Bv[r], s[3][r], A[r] * c[3][r]);
        }
    }

    // out1: wires {0,2,3}
    {
        float q00[R], q10[R], q01[R], q11[R];
        #pragma unroll
        for (int r = 0; r < R; r++) {
            q00[r] = c[2][r] * c[3][r];
            q10[r] = s[2][r] * c[3][r];
            q01[r] = c[2][r] * s[3][r];
            q11[r] = s[2][r] * s[3][r];
        }
        float k0 = C[0][1], k4 = C[4][1], k8 = C[8][1], k12 = C[12][1];
        float k1 = C[1][1], k5 = C[5][1], k9 = C[9][1], k13 = C[13][1];
        #pragma unroll
        for (int r = 0; r < R; r++) {
            float a = k0 * q00[r];
            a = fmaf(k4,  q10[r], a);
            a = fmaf(k8,  q01[r], a);
            a = fmaf(k12, q11[r], a);
            float b = k1 * q00[r];
            b = fmaf(k5,  q10[r], b);
            b = fmaf(k9,  q01[r], b);
            b = fmaf(k13, q11[r], b);
            o[r][1] = fmaf(b, s[0][r], a * c[0][r]);
        }
    }

    // out2: wires {1,3}
    {
        float k0 = C[0][2], k2 = C[2][2], k8 = C[8][2], k10 = C[10][2];
        #pragma unroll
        for (int r = 0; r < R; r++) {
            float v = k0 * (c[1][r] * c[3][r]);
            v = fmaf(k2,  s[1][r] * c[3][r], v);
            v = fmaf(k8,  c[1][r] * s[3][r], v);
            v = fmaf(k10, s[1][r] * s[3][r], v);
            o[r][2] = v;
        }
    }

    // out3: wires {0,2}
    {
        float k0 = C[0][3], k1 = C[1][3], k4 = C[4][3], k5 = C[5][3];
        #pragma unroll
        for (int r = 0; r < R; r++) {
            float v = k0 * (c[0][r] * c[2][r]);
            v = fmaf(k1, s[0][r] * c[2][r], v);
            v = fmaf(k4, c[0][r] * s[2][r], v);
            v = fmaf(k5, s[0][r] * s[2][r], v);
            o[r][3] = v;
        }
    }
}

__global__ void __launch_bounds__(128, 4) hqnn_main(const float4* __restrict__ xv,
                                                    float4* __restrict__ out, int B) {
    int base = blockIdx.x * (128 * R) + threadIdx.x;

    int rows[R];
    #pragma unroll
    for (int k = 0; k < R; k++) rows[k] = base + k * 128;

    // Front-batched input load (MLP = 16 LDG.128)
    float Xs[R][16];
    #pragma unroll
    for (int k = 0; k < R; k++) {
        if (rows[k] < B) {
            const float4* p = xv + (size_t)rows[k] * 4;
            float4 a = p[0], b = p[1], cc = p[2], d = p[3];
            Xs[k][0]  = a.x;  Xs[k][1]  = a.y;  Xs[k][2]  = a.z;  Xs[k][3]  = a.w;
            Xs[k][4]  = b.x;  Xs[k][5]  = b.y;  Xs[k][6]  = b.z;  Xs[k][7]  = b.w;
            Xs[k][8]  = cc.x; Xs[k][9]  = cc.y; Xs[k][10] = cc.z; Xs[k][11] = cc.w;
            Xs[k][12] = d.x;  Xs[k][13] = d.y;  Xs[k][14] = d.z;  Xs[k][15] = d.w;
        } else {
            #pragma unroll
            for (int i = 0; i < 16; i++) Xs[k][i] = 0.f;
        }
    }

    // dense0 (16 -> 4), constant-major: one LDCU feeds R FFMAs
    float acc[R][4];
    #pragma unroll
    for (int j = 0; j < 4; j++) {
        float bj = cK.b0[j];
        #pragma unroll
        for (int r = 0; r < R; r++) acc[r][j] = bj;
    }
    #pragma unroll
    for (int i = 0; i < 16; i++) {
        #pragma unroll
        for (int j = 0; j < 4; j++) {
            float w = cK.W0[i][j];
            #pragma unroll
            for (int r = 0; r < R; r++)
                acc[r][j] = fmaf(Xs[r][i], w, acc[r][j]);
        }
    }

    float h[R][4], o[R][4];
    #pragma unroll
    for (int r = 0; r < R; r++)
        #pragma unroll
        for (int j = 0; j < 4; j++)
            h[r][j] = tanh_fast(acc[r][j]);

    qcirc4(cK.C[0], h, o);

    // dense1 (4 -> 4) + tanh
    #pragma unroll
    for (int j = 0; j < 4; j++) {
        float bj = cK.b1[j];
        #pragma unroll
        for (int r = 0; r < R; r++) acc[r][j] = bj;
    }
    #pragma unroll
    for (int i = 0; i < 4; i++) {
        #pragma unroll
        for (int j = 0; j < 4; j++) {
            float w = cK.W1[i][j];
            #pragma unroll
            for (int r = 0; r < R; r++)
                acc[r][j] = fmaf(o[r][i], w, acc[r][j]);
        }
    }
    #pragma unroll
    for (int r = 0; r < R; r++)
        #pragma unroll
        for (int j = 0; j < 4; j++)
            h[r][j] = tanh_fast(acc[r][j]);

    qcirc4(cK.C[1], h, o);

    // dense2 (4 -> 4) + tanh
    #pragma unroll
    for (int j = 0; j < 4; j++) {
        float bj = cK.b2[j];
        #pragma unroll
        for (int r = 0; r < R; r++) acc[r][j] = bj;
    }
    #pragma unroll
    for (int i = 0; i < 4; i++) {
        #pragma unroll
        for (int j = 0; j < 4; j++) {
            float w = cK.W2[i][j];
            #pragma unroll
            for (int r = 0; r < R; r++)
                acc[r][j] = fmaf(o[r][i], w, acc[r][j]);
        }
    }
    #pragma unroll
    for (int r = 0; r < R; r++)
        #pragma unroll
        for (int j = 0; j < 4; j++)
            h[r][j] = tanh_fast(acc[r][j]);

    qcirc4(cK.C[2], h, o);

    #pragma unroll
    for (int k = 0; k < R; k++) {
        if (rows[k] < B)
            out[rows[k]] = make_float4(o[k][0], o[k][1], o[k][2], o[k][3]);
    }
}

// ------------------------------ launch --------------------------------------

extern "C" void kernel_launch(void* const* d_in, const int* in_sizes, int n_in,
                              void* d_out, int out_size) {
    const float* x     = (const float*)d_in[0];
    const float* theta = (const float*)d_in[1];
    const float* W0    = (const float*)d_in[2];
    const float* b0    = (const float*)d_in[3];
    const float* W1    = (const float*)d_in[4];
    const float* b1    = (const float*)d_in[5];
    const float* W2    = (const float*)d_in[6];
    const float* b2    = (const float*)d_in[7];
    int B = in_sizes[0] / 16;

    hqnn_setup<<<1, 128>>>(theta, W0, b0, W1, b1, W2, b2);

    void* stage_ptr = nullptr;
    cudaGetSymbolAddress(&stage_ptr, g_stage);
    cudaMemcpyToSymbolAsync(cK, stage_ptr, sizeof(ConstsLayout), 0,
                            cudaMemcpyDeviceToDevice, 0);

    int rowsPerBlock = 128 * R;
    int blocks = (B + rowsPerBlock - 1) / rowsPerBlock;
    hqnn_main<<<blocks, 128>>>((const float4*)x, (float4*)d_out, B);
}

// round 15
// speedup vs baseline: 1.0135x; 1.0118x over previous
#include <cuda_runtime.h>
#include <cstdint>

// ---------------------------------------------------------------------------
// HQNN: 3x (Dense+tanh -> 4-qubit RX/CNOT circuit).
// Analytic multilinear reformulation (supports T0={0,1,3} T1={0,2,3}
// T2={1,3} T3={0,2}); coefficients probed per launch by a tiny setup kernel.
// R9: 4 rows per thread, constant-major scheduling so each LDCU feeds 4 FFMAs
// (sm_103a has no cbank-fused FFMA operands; constant reads are explicit LDCU
// and dominated the issue stream at R=1).
// ---------------------------------------------------------------------------

struct ConstsLayout {
    float C[3][16][4];   // probe table: C[layer][mask][wire]
    float W0[16][4];
    float b0[4];
    float W1[4][4];
    float b1[4];
    float W2[4][4];
    float b2[4];
};   // 300 floats

__device__ float g_stage[300];
__constant__ ConstsLayout cK;

// ------------------------- setup: probe simulations ------------------------

__device__ void rx_apply(float* re, float* im, float ang, int w) {
    float c = cosf(0.5f * ang);
    float s = sinf(0.5f * ang);
    int bit = 1 << w;
    for (int b = 0; b < 16; b++) {
        if (b & bit) continue;
        int b1 = b | bit;
        float r0 = re[b], i0 = im[b], r1 = re[b1], i1 = im[b1];
        re[b]  = c * r0 + s * i1;
        im[b]  = c * i0 - s * r1;
        re[b1] = c * r1 + s * i0;
        im[b1] = c * i1 - s * r0;
    }
}

__device__ void cnot_apply(float* re, float* im, int cw, int tw) {
    int cb = 1 << cw, tb = 1 << tw;
    for (int b = 0; b < 16; b++) {
        if ((b & cb) && !(b & tb)) {
            int b1 = b | tb;
            float t;
            t = re[b]; re[b] = re[b1]; re[b1] = t;
            t = im[b]; im[b] = im[b1]; im[b1] = t;
        }
    }
}

__global__ void hqnn_setup(const float* __restrict__ theta,
                           const float* __restrict__ W0, const float* __restrict__ b0,
                           const float* __restrict__ W1, const float* __restrict__ b1,
                           const float* __restrict__ W2, const float* __restrict__ b2) {
    int t = threadIdx.x;
    if (t < 48) {
        int l = t >> 4;      // hybrid layer 0..2
        int m = t & 15;      // probe mask over 4 wires
        float re[16], im[16];
        #pragma unroll
        for (int i = 0; i < 16; i++) { re[i] = 0.f; im[i] = 0.f; }
        re[0] = 1.f;
        for (int w = 0; w < 4; w++) {
            float a = ((m >> w) & 1) ? 1.57079632679489662f : 0.0f;
            rx_apply(re, im, a, w);
        }
        for (int e = 0; e < 2; e++) {
            for (int w = 0; w < 4; w++)
                rx_apply(re, im, theta[l * 8 + e * 4 + w], w);
            for (int w = 0; w < 4; w++)
                cnot_apply(re, im, w, (w + 1) & 3);
        }
        for (int w = 0; w < 4; w++) {
            float z = 0.f;
            for (int b = 0; b < 16; b++) {
                float p = re[b] * re[b] + im[b] * im[b];
                z += ((b >> w) & 1) ? -p : p;
            }
            g_stage[(l * 16 + m) * 4 + w] = z;
        }
    }
    for (int i = t; i < 108; i += blockDim.x) {
        float v;
        if (i < 64)       v = W0[i];
        else if (i < 68)  v = b0[i - 64];
        else if (i < 84)  v = W1[i - 68];
        else if (i < 88)  v = b1[i - 84];
        else if (i < 104) v = W2[i - 88];
        else              v = b2[i - 104];
        g_stage[192 + i] = v;
    }
}

// ------------------------------ main kernel --------------------------------

#define R 4   // rows per thread

__device__ __forceinline__ float tanh_fast(float x) {
    float e = __expf(2.0f * x);
    return 1.0f - __fdividef(2.0f, e + 1.0f);
}

// Constant-major 4-row circuit evaluation. h[r][wire] in, o[r][wire] out.
__device__ __forceinline__ void qcirc4(const float (&C)[16][4],
                                       const float (&h)[R][4], float (&o)[R][4]) {
    float s[4][R], c[4][R];   // [wire][row]
    #pragma unroll
    for (int r = 0; r < R; r++) {
        #pragma unroll
        for (int w = 0; w < 4; w++)
            __sincosf(h[r][w], &s[w][r], &c[w][r]);
    }

    // out0: wires {0,1,3}
    {
        float p00[R], p10[R], p01[R], p11[R], A[R], Bv[R];
        #pragma unroll
        for (int r = 0; r < R; r++) {
            p00[r] = c[0][r] * c[1][r];
            p10[r] = s[0][r] * c[1][r];
            p01[r] = c[0][r] * s[1][r];
            p11[r] = s[0][r] * s[1][r];
        }
        float k0 = C[0][0], k1 = C[1][0], k2 = C[2][0], k3 = C[3][0];
        float k8 = C[8][0], k9 = C[9][0], k10 = C[10][0], k11 = C[11][0];
        #pragma unroll
        for (int r = 0; r < R; r++) {
            float a = k0 * p00[r];
            a = fmaf(k1, p10[r], a);
            a = fmaf(k2, p01[r], a);
            a = fmaf(k3, p11[r], a);
            A[r] = a;
            float b = k8 * p00[r];
            b = fmaf(k9,  p10[r], b);
            b = fmaf(k10, p01[r], b);
            b = fmaf(k11, p11[r], b);
            Bv[r] = b;
            o[r][0] = fmaf(Bv[r], s[3][r], A[r] * c[3][r]);
        }
    }

    // out1: wires {0,2,3}
    {
        float q00[R], q10[R], q01[R], q11[R];
        #pragma unroll
        for (int r = 0; r < R; r++) {
            q00[r] = c[2][r] * c[3][r];
            q10[r] = s[2][r] * c[3][r];
            q01[r] = c[2][r] * s[3][r];
            q11[r] = s[2][r] * s[3][r];
        }
        float k0 = C[0][1], k4 = C[4][1], k8 = C[8][1], k12 = C[12][1];
        float k1 = C[1][1], k5 = C[5][1], k9 = C[9][1], k13 = C[13][1];
        #pragma unroll
        for (int r = 0; r < R; r++) {
            float a = k0 * q00[r];
            a = fmaf(k4,  q10[r], a);
            a = fmaf(k8,  q01[r], a);
            a = fmaf(k12, q11[r], a);
            float b = k1 * q00[r];
            b = fmaf(k5,  q10[r], b);
            b = fmaf(k9,  q01[r], b);
            b = fmaf(k13, q11[r], b);
            o[r][1] = fmaf(b, s[0][r], a * c[0][r]);
        }
    }

    // out2: wires {1,3}
    {
        float k0 = C[0][2], k2 = C[2][2], k8 = C[8][2], k10 = C[10][2];
        #pragma unroll
        for (int r = 0; r < R; r++) {
            float v = k0 * (c[1][r] * c[3][r]);
            v = fmaf(k2,  s[1][r] * c[3][r], v);
            v = fmaf(k8,  c[1][r] * s[3][r], v);
            v = fmaf(k10, s[1][r] * s[3][r], v);
            o[r][2] = v;
        }
    }

    // out3: wires {0,2}
    {
        float k0 = C[0][3], k1 = C[1][3], k4 = C[4][3], k5 = C[5][3];
        #pragma unroll
        for (int r = 0; r < R; r++) {
            float v = k0 * (c[0][r] * c[2][r]);
            v = fmaf(k1, s[0][r] * c[2][r], v);
            v = fmaf(k4, c[0][r] * s[2][r], v);
            v = fmaf(k5, s[0][r] * s[2][r], v);
            o[r][3] = v;
        }
    }
}

__global__ void __launch_bounds__(128, 4) hqnn_main(const float4* __restrict__ xv,
                                                    float4* __restrict__ out, int B) {
    int base = blockIdx.x * (128 * R) + threadIdx.x;

    int rows[R];
    #pragma unroll
    for (int k = 0; k < R; k++) rows[k] = base + k * 128;

    // Front-batched input load (MLP = 16 LDG.128)
    float Xs[R][16];
    #pragma unroll
    for (int k = 0; k < R; k++) {
        if (rows[k] < B) {
            const float4* p = xv + (size_t)rows[k] * 4;
            float4 a = p[0], b = p[1], cc = p[2], d = p[3];
            Xs[k][0]  = a.x;  Xs[k][1]  = a.y;  Xs[k][2]  = a.z;  Xs[k][3]  = a.w;
            Xs[k][4]  = b.x;  Xs[k][5]  = b.y;  Xs[k][6]  = b.z;  Xs[k][7]  = b.w;
            Xs[k][8]  = cc.x; Xs[k][9]  = cc.y; Xs[k][10] = cc.z; Xs[k][11] = cc.w;
            Xs[k][12] = d.x;  Xs[k][13] = d.y;  Xs[k][14] = d.z;  Xs[k][15] = d.w;
        } else {
            #pragma unroll
            for (int i = 0; i < 16; i++) Xs[k][i] = 0.f;
        }
    }

    // dense0 (16 -> 4), constant-major: one LDCU feeds R FFMAs
    float acc[R][4];
    #pragma unroll
    for (int j = 0; j < 4; j++) {
        float bj = cK.b0[j];
        #pragma unroll
        for (int r = 0; r < R; r++) acc[r][j] = bj;
    }
    #pragma unroll
    for (int i = 0; i < 16; i++) {
        #pragma unroll
        for (int j = 0; j < 4; j++) {
            float w = cK.W0[i][j];
            #pragma unroll
            for (int r = 0; r < R; r++)
                acc[r][j] = fmaf(Xs[r][i], w, acc[r][j]);
        }
    }

    float h[R][4], o[R][4];
    #pragma unroll
    for (int r = 0; r < R; r++)
        #pragma unroll
        for (int j = 0; j < 4; j++)
            h[r][j] = tanh_fast(acc[r][j]);

    qcirc4(cK.C[0], h, o);

    // dense1 (4 -> 4) + tanh
    #pragma unroll
    for (int j = 0; j < 4; j++) {
        float bj = cK.b1[j];
        #pragma unroll
        for (int r = 0; r < R; r++) acc[r][j] = bj;
    }
    #pragma unroll
    for (int i = 0; i < 4; i++) {
        #pragma unroll
        for (int j = 0; j < 4; j++) {
            float w = cK.W1[i][j];
            #pragma unroll
            for (int r = 0; r < R; r++)
                acc[r][j] = fmaf(o[r][i], w, acc[r][j]);
        }
    }
    #pragma unroll
    for (int r = 0; r < R; r++)
        #pragma unroll
        for (int j = 0; j < 4; j++)
            h[r][j] = tanh_fast(acc[r][j]);

    qcirc4(cK.C[1], h, o);

    // dense2 (4 -> 4) + tanh
    #pragma unroll
    for (int j = 0; j < 4; j++) {
        float bj = cK.b2[j];
        #pragma unroll
        for (int r = 0; r < R; r++) acc[r][j] = bj;
    }
    #pragma unroll
    for (int i = 0; i < 4; i++) {
        #pragma unroll
        for (int j = 0; j < 4; j++) {
            float w = cK.W2[i][j];
            #pragma unroll
            for (int r = 0; r < R; r++)
                acc[r][j] = fmaf(o[r][i], w, acc[r][j]);
        }
    }
    #pragma unroll
    for (int r = 0; r < R; r++)
        #pragma unroll
        for (int j = 0; j < 4; j++)
            h[r][j] = tanh_fast(acc[r][j]);

    qcirc4(cK.C[2], h, o);

    #pragma unroll
    for (int k = 0; k < R; k++) {
        if (rows[k] < B)
            out[rows[k]] = make_float4(o[k][0], o[k][1], o[k][2], o[k][3]);
    }
}

// ------------------------------ launch --------------------------------------

extern "C" void kernel_launch(void* const* d_in, const int* in_sizes, int n_in,
                              void* d_out, int out_size) {
    const float* x     = (const float*)d_in[0];
    const float* theta = (const float*)d_in[1];
    const float* W0    = (const float*)d_in[2];
    const float* b0    = (const float*)d_in[3];
    const float* W1    = (const float*)d_in[4];
    const float* b1    = (const float*)d_in[5];
    const float* W2    = (const float*)d_in[6];
    const float* b2    = (const float*)d_in[7];
    int B = in_sizes[0] / 16;

    hqnn_setup<<<1, 128>>>(theta, W0, b0, W1, b1, W2, b2);

    void* stage_ptr = nullptr;
    cudaGetSymbolAddress(&stage_ptr, g_stage);
    cudaMemcpyToSymbolAsync(cK, stage_ptr, sizeof(ConstsLayout), 0,
                            cudaMemcpyDeviceToDevice, 0);

    int rowsPerBlock = 128 * R;
    int blocks = (B + rowsPerBlock - 1) / rowsPerBlock;
    hqnn_main<<<blocks, 128>>>((const float4*)x, (float4*)d_out, B);
}